// round 4
// baseline (speedup 1.0000x reference)
#include <cuda_runtime.h>
#include <cuda_bf16.h>
#include <math.h>

// Problem constants (fixed shapes for this problem)
#define NBOX  4096
#define IMG_H 512
#define IMG_W 512
#define IMG_C 64

// Scratch (no cudaMalloc allowed)
__device__ float g_x1[NBOX * 2048];   // conv2 output, flattened
__device__ float g_h1[NBOX * 512];    // d1 output
__device__ float g_h2[NBOX * 512];    // d2 output

// ---------------------------------------------------------------------------
// K1: fused crop_and_resize * proposal -> conv1(s2,relu) -> conv2(s2,relu)
// One CTA per box. smem: x0[16][16][64] (64KB) + c1[8][8][128] (32KB).
// ---------------------------------------------------------------------------
__global__ __launch_bounds__(256, 2) void k_backbone(
    const float* __restrict__ feat, const float* __restrict__ prop,
    const float* __restrict__ boxes, const int* __restrict__ bidx,
    const float* __restrict__ w1, const float* __restrict__ b1,
    const float* __restrict__ w2, const float* __restrict__ b2,
    float* __restrict__ xout)
{
    extern __shared__ float smem[];
    float* s_x0 = smem;                 // 16*16*64 = 16384 floats
    float* s_c1 = smem + 16 * 16 * 64;  // 8*8*128  =  8192 floats

    const int box = blockIdx.x;
    const int t = threadIdx.x;

    const float by1 = boxes[box * 4 + 0];
    const float bx1 = boxes[box * 4 + 1];
    const float by2 = boxes[box * 4 + 2];
    const float bx2 = boxes[box * 4 + 3];
    const int b = bidx[box];

    // ---- Stage 1: bilinear crop (features) * bilinear crop (proposal) ----
    {
        const int gy = t >> 4, gx = t & 15;
        const float ys = (by1 + ((float)gy / 15.f) * (by2 - by1)) * 511.f;
        const float xs = (bx1 + ((float)gx / 15.f) * (bx2 - bx1)) * 511.f;
        const float y0f = floorf(ys), x0f = floorf(xs);
        const float wy = ys - y0f, wx = xs - x0f;
        int iy0 = (int)y0f; iy0 = iy0 < 0 ? 0 : (iy0 > 511 ? 511 : iy0);
        int ix0 = (int)x0f; ix0 = ix0 < 0 ? 0 : (ix0 > 511 ? 511 : ix0);
        const int iy1 = iy0 + 1 > 511 ? 511 : iy0 + 1;
        const int ix1 = ix0 + 1 > 511 ? 511 : ix0 + 1;

        const size_t base = (size_t)b * IMG_H * IMG_W;
        const float p00 = prop[base + (size_t)iy0 * IMG_W + ix0];
        const float p01 = prop[base + (size_t)iy0 * IMG_W + ix1];
        const float p10 = prop[base + (size_t)iy1 * IMG_W + ix0];
        const float p11 = prop[base + (size_t)iy1 * IMG_W + ix1];
        const float omwx = 1.f - wx, omwy = 1.f - wy;
        const float pv = (p00 * omwx + p01 * wx) * omwy
                       + (p10 * omwx + p11 * wx) * wy;

        const float4* f00 = (const float4*)(feat + (base + (size_t)iy0 * IMG_W + ix0) * IMG_C);
        const float4* f01 = (const float4*)(feat + (base + (size_t)iy0 * IMG_W + ix1) * IMG_C);
        const float4* f10 = (const float4*)(feat + (base + (size_t)iy1 * IMG_W + ix0) * IMG_C);
        const float4* f11 = (const float4*)(feat + (base + (size_t)iy1 * IMG_W + ix1) * IMG_C);
        float4* dst = (float4*)(s_x0 + t * 64);
        #pragma unroll
        for (int cb = 0; cb < 16; cb++) {
            float4 a = f00[cb], c = f01[cb], d = f10[cb], e = f11[cb];
            float4 r;
            r.x = ((a.x * omwx + c.x * wx) * omwy + (d.x * omwx + e.x * wx) * wy) * pv;
            r.y = ((a.y * omwx + c.y * wx) * omwy + (d.y * omwx + e.y * wx) * wy) * pv;
            r.z = ((a.z * omwx + c.z * wx) * omwy + (d.z * omwx + e.z * wx) * wy) * pv;
            r.w = ((a.w * omwx + c.w * wx) * omwy + (d.w * omwx + e.w * wx) * wy) * pv;
            dst[cb] = r;
        }
    }
    __syncthreads();

    // ---- Stage 2: conv1 3x3 s2 SAME (pad lo=0, hi=1), 64->128, relu ----
    // thread: ocg = t%16 -> 8 ocs, pset = t/16 -> 4 spatial positions
    {
        const int ocg = t & 15;
        const int oc0 = ocg * 8;
        const int pset = t >> 4;
        int oyv[4], oxv[4];
        #pragma unroll
        for (int j = 0; j < 4; j++) {
            int pos = pset * 4 + j;
            oyv[j] = pos >> 3; oxv[j] = pos & 7;
        }
        float acc[4][8];
        {
            float4 bb0 = __ldg((const float4*)(b1 + oc0));
            float4 bb1 = __ldg((const float4*)(b1 + oc0 + 4));
            #pragma unroll
            for (int j = 0; j < 4; j++) {
                acc[j][0] = bb0.x; acc[j][1] = bb0.y; acc[j][2] = bb0.z; acc[j][3] = bb0.w;
                acc[j][4] = bb1.x; acc[j][5] = bb1.y; acc[j][6] = bb1.z; acc[j][7] = bb1.w;
            }
        }
        #pragma unroll 1
        for (int ky = 0; ky < 3; ky++) {
            #pragma unroll 1
            for (int kx = 0; kx < 3; kx++) {
                const float* wbase = w1 + (size_t)((ky * 3 + kx) * 64) * 128 + oc0;
                int ib[4]; bool vl[4];
                #pragma unroll
                for (int j = 0; j < 4; j++) {
                    int iy = 2 * oyv[j] + ky, ix = 2 * oxv[j] + kx;
                    vl[j] = (iy < 16) && (ix < 16);
                    ib[j] = (iy * 16 + ix) * 64;   // OOB stays inside 96KB smem; masked below
                }
                #pragma unroll 4
                for (int ic = 0; ic < 64; ic += 4) {
                    float in_s[4][4];
                    #pragma unroll
                    for (int j = 0; j < 4; j++) {
                        float4 v = vl[j] ? *(const float4*)(s_x0 + ib[j] + ic)
                                         : make_float4(0.f, 0.f, 0.f, 0.f);
                        in_s[j][0] = v.x; in_s[j][1] = v.y; in_s[j][2] = v.z; in_s[j][3] = v.w;
                    }
                    #pragma unroll
                    for (int q = 0; q < 4; q++) {
                        float4 wa = __ldg((const float4*)(wbase + (ic + q) * 128));
                        float4 wb = __ldg((const float4*)(wbase + (ic + q) * 128 + 4));
                        #pragma unroll
                        for (int j = 0; j < 4; j++) {
                            float v = in_s[j][q];
                            acc[j][0] = fmaf(v, wa.x, acc[j][0]);
                            acc[j][1] = fmaf(v, wa.y, acc[j][1]);
                            acc[j][2] = fmaf(v, wa.z, acc[j][2]);
                            acc[j][3] = fmaf(v, wa.w, acc[j][3]);
                            acc[j][4] = fmaf(v, wb.x, acc[j][4]);
                            acc[j][5] = fmaf(v, wb.y, acc[j][5]);
                            acc[j][6] = fmaf(v, wb.z, acc[j][6]);
                            acc[j][7] = fmaf(v, wb.w, acc[j][7]);
                        }
                    }
                }
            }
        }
        #pragma unroll
        for (int j = 0; j < 4; j++) {
            int pos = pset * 4 + j;
            float* d = s_c1 + pos * 128 + oc0;
            ((float4*)d)[0] = make_float4(fmaxf(acc[j][0], 0.f), fmaxf(acc[j][1], 0.f),
                                          fmaxf(acc[j][2], 0.f), fmaxf(acc[j][3], 0.f));
            ((float4*)d)[1] = make_float4(fmaxf(acc[j][4], 0.f), fmaxf(acc[j][5], 0.f),
                                          fmaxf(acc[j][6], 0.f), fmaxf(acc[j][7], 0.f));
        }
    }
    __syncthreads();

    // ---- Stage 3: conv2 3x3 s2 SAME (pad lo=0, hi=1), 128->128, relu ----
    // thread: ocg = t%16 -> 8 ocs, pos = t/16 (0..15)
    {
        const int ocg = t & 15;
        const int oc0 = ocg * 8;
        const int pos = t >> 4;
        const int oy = pos >> 2, ox = pos & 3;
        float acc2[8];
        {
            float4 bb0 = __ldg((const float4*)(b2 + oc0));
            float4 bb1 = __ldg((const float4*)(b2 + oc0 + 4));
            acc2[0] = bb0.x; acc2[1] = bb0.y; acc2[2] = bb0.z; acc2[3] = bb0.w;
            acc2[4] = bb1.x; acc2[5] = bb1.y; acc2[6] = bb1.z; acc2[7] = bb1.w;
        }
        #pragma unroll 1
        for (int ky = 0; ky < 3; ky++) {
            #pragma unroll 1
            for (int kx = 0; kx < 3; kx++) {
                const int iy = 2 * oy + ky, ix = 2 * ox + kx;
                if (iy > 7 || ix > 7) continue;
                const float* inb = s_c1 + (iy * 8 + ix) * 128;
                const float* wbase = w2 + (size_t)((ky * 3 + kx) * 128) * 128 + oc0;
                #pragma unroll 4
                for (int ic = 0; ic < 128; ic += 4) {
                    float4 v = *(const float4*)(inb + ic);
                    float in4[4] = {v.x, v.y, v.z, v.w};
                    #pragma unroll
                    for (int q = 0; q < 4; q++) {
                        float4 wa = __ldg((const float4*)(wbase + (ic + q) * 128));
                        float4 wb = __ldg((const float4*)(wbase + (ic + q) * 128 + 4));
                        float vv = in4[q];
                        acc2[0] = fmaf(vv, wa.x, acc2[0]);
                        acc2[1] = fmaf(vv, wa.y, acc2[1]);
                        acc2[2] = fmaf(vv, wa.z, acc2[2]);
                        acc2[3] = fmaf(vv, wa.w, acc2[3]);
                        acc2[4] = fmaf(vv, wb.x, acc2[4]);
                        acc2[5] = fmaf(vv, wb.y, acc2[5]);
                        acc2[6] = fmaf(vv, wb.z, acc2[6]);
                        acc2[7] = fmaf(vv, wb.w, acc2[7]);
                    }
                }
            }
        }
        float* o = xout + (size_t)box * 2048 + pos * 128 + oc0;
        ((float4*)o)[0] = make_float4(fmaxf(acc2[0], 0.f), fmaxf(acc2[1], 0.f),
                                      fmaxf(acc2[2], 0.f), fmaxf(acc2[3], 0.f));
        ((float4*)o)[1] = make_float4(fmaxf(acc2[4], 0.f), fmaxf(acc2[5], 0.f),
                                      fmaxf(acc2[6], 0.f), fmaxf(acc2[7], 0.f));
    }
}

// ---------------------------------------------------------------------------
// GEMM: C[M,N] = act(A[M,K] @ B[K,N] + bias). 64x64 tile, 256 threads, 4x4/thr.
// M,N multiples of 64; K multiple of 16.
// ---------------------------------------------------------------------------
template <int RELU>
__global__ __launch_bounds__(256) void k_gemm(
    const float* __restrict__ A, const float* __restrict__ Bm,
    const float* __restrict__ bias, float* __restrict__ Cm,
    int M, int N, int K)
{
    __shared__ float As[16][68];
    __shared__ float Bs[16][68];
    const int tid = threadIdx.x;
    const int m0 = blockIdx.x * 64, n0 = blockIdx.y * 64;
    const int tr = tid >> 4, tc = tid & 15;
    const int lam = tid >> 2, lak = (tid & 3) * 4;
    const int lbk = tid >> 4, lbn = (tid & 15) * 4;

    float acc[4][4];
    #pragma unroll
    for (int i = 0; i < 4; i++)
        #pragma unroll
        for (int j = 0; j < 4; j++) acc[i][j] = 0.f;

    const float* Ap = A + (size_t)(m0 + lam) * K + lak;
    const float* Bp = Bm + (size_t)lbk * N + n0 + lbn;

    for (int k0 = 0; k0 < K; k0 += 16) {
        float4 a = *(const float4*)(Ap + k0);
        float4 bv = *(const float4*)(Bp + (size_t)k0 * N);
        __syncthreads();
        As[lak + 0][lam] = a.x; As[lak + 1][lam] = a.y;
        As[lak + 2][lam] = a.z; As[lak + 3][lam] = a.w;
        *(float4*)&Bs[lbk][lbn] = bv;
        __syncthreads();
        #pragma unroll
        for (int k = 0; k < 16; k++) {
            float4 av = *(const float4*)&As[k][tr * 4];
            float4 bb = *(const float4*)&Bs[k][tc * 4];
            float a4[4] = {av.x, av.y, av.z, av.w};
            float b4[4] = {bb.x, bb.y, bb.z, bb.w};
            #pragma unroll
            for (int i = 0; i < 4; i++)
                #pragma unroll
                for (int j = 0; j < 4; j++)
                    acc[i][j] = fmaf(a4[i], b4[j], acc[i][j]);
        }
    }

    float4 bvq = __ldg((const float4*)(bias + n0 + tc * 4));
    float bias4[4] = {bvq.x, bvq.y, bvq.z, bvq.w};
    #pragma unroll
    for (int i = 0; i < 4; i++) {
        float4 r;
        float v0 = acc[i][0] + bias4[0];
        float v1 = acc[i][1] + bias4[1];
        float v2 = acc[i][2] + bias4[2];
        float v3 = acc[i][3] + bias4[3];
        if (RELU) { v0 = fmaxf(v0, 0.f); v1 = fmaxf(v1, 0.f); v2 = fmaxf(v2, 0.f); v3 = fmaxf(v3, 0.f); }
        r.x = v0; r.y = v1; r.z = v2; r.w = v3;
        *(float4*)(Cm + (size_t)(m0 + tr * 4 + i) * N + n0 + tc * 4) = r;
    }
}

// ---------------------------------------------------------------------------
// K4: heads — reg/score dots (warp per box), class select, box decode.
// out = [scores (Nb) | regressions (Nb*4) | bboxes (Nb*4)]
// ---------------------------------------------------------------------------
__global__ __launch_bounds__(256) void k_heads(
    const float* __restrict__ X, const float* __restrict__ boxes,
    const int* __restrict__ cls, const float* __restrict__ regw,
    const float* __restrict__ regb, const float* __restrict__ scw,
    const float* __restrict__ scb, float* __restrict__ out, int Nb)
{
    const int gw = (blockIdx.x * blockDim.x + threadIdx.x) >> 5;
    const int lane = threadIdx.x & 31;
    if (gw >= Nb) return;
    const float* x = X + (size_t)gw * 512;

    float acc[12], sc[3];
    #pragma unroll
    for (int c = 0; c < 12; c++) acc[c] = 0.f;
    #pragma unroll
    for (int c = 0; c < 3; c++) sc[c] = 0.f;

    for (int j = lane; j < 512; j += 32) {
        float xv = x[j];
        const float* wr = regw + j * 12;
        #pragma unroll
        for (int c = 0; c < 12; c++) acc[c] = fmaf(xv, __ldg(wr + c), acc[c]);
        const float* ws = scw + j * 3;
        #pragma unroll
        for (int c = 0; c < 3; c++) sc[c] = fmaf(xv, __ldg(ws + c), sc[c]);
    }
    #pragma unroll
    for (int c = 0; c < 12; c++)
        for (int s = 16; s; s >>= 1) acc[c] += __shfl_xor_sync(0xffffffffu, acc[c], s);
    #pragma unroll
    for (int c = 0; c < 3; c++)
        for (int s = 16; s; s >>= 1) sc[c] += __shfl_xor_sync(0xffffffffu, sc[c], s);

    if (lane == 0) {
        const int cl = cls[gw];
        float r[4];
        #pragma unroll
        for (int k = 0; k < 4; k++) {
            float v = (cl == 0) ? acc[k] : (cl == 1) ? acc[4 + k] : acc[8 + k];
            r[k] = v + regb[cl * 4 + k];
        }
        float score = ((cl == 0) ? sc[0] : (cl == 1) ? sc[1] : sc[2]) + scb[cl];

        const float y1 = boxes[gw * 4 + 0], x1 = boxes[gw * 4 + 1];
        const float y2 = boxes[gw * 4 + 2], x2 = boxes[gw * 4 + 3];
        const float h = y2 - y1, w = x2 - x1;
        const float cy = y1 + 0.5f * h + r[0] * h;
        const float cx = x1 + 0.5f * w + r[1] * w;
        const float nh = h * expf(r[2]);
        const float nw = w * expf(r[3]);

        out[gw] = score;
        float* ro = out + Nb + (size_t)gw * 4;
        ro[0] = r[0]; ro[1] = r[1]; ro[2] = r[2]; ro[3] = r[3];
        float* bo = out + (size_t)Nb * 5 + (size_t)gw * 4;
        bo[0] = cy - 0.5f * nh; bo[1] = cx - 0.5f * nw;
        bo[2] = cy + 0.5f * nh; bo[3] = cx + 0.5f * nw;
    }
}

// ---------------------------------------------------------------------------
extern "C" void kernel_launch(void* const* d_in, const int* in_sizes, int n_in,
                              void* d_out, int out_size)
{
    const float* features = (const float*)d_in[0];
    const float* proposal = (const float*)d_in[1];
    const float* bboxes   = (const float*)d_in[2];
    const int*   box_idx  = (const int*)d_in[3];
    const int*   cls      = (const int*)d_in[4];
    const float* c1w      = (const float*)d_in[5];
    const float* c1b      = (const float*)d_in[6];
    const float* c2w      = (const float*)d_in[7];
    const float* c2b      = (const float*)d_in[8];
    const float* d1w      = (const float*)d_in[9];
    const float* d1b      = (const float*)d_in[10];
    const float* d2w      = (const float*)d_in[11];
    const float* d2b      = (const float*)d_in[12];
    const float* regw     = (const float*)d_in[13];
    const float* regb     = (const float*)d_in[14];
    const float* scw      = (const float*)d_in[15];
    const float* scb      = (const float*)d_in[16];
    float* out = (float*)d_out;

    const int Nb = in_sizes[3];  // number of boxes (4096)

    void *px1, *ph1, *ph2;
    cudaGetSymbolAddress(&px1, g_x1);
    cudaGetSymbolAddress(&ph1, g_h1);
    cudaGetSymbolAddress(&ph2, g_h2);

    const int smem_k1 = (16 * 16 * 64 + 8 * 8 * 128) * 4;  // 98304 bytes
    cudaFuncSetAttribute(k_backbone, cudaFuncAttributeMaxDynamicSharedMemorySize, smem_k1);

    k_backbone<<<Nb, 256, smem_k1>>>(features, proposal, bboxes, box_idx,
                                     c1w, c1b, c2w, c2b, (float*)px1);

    k_gemm<1><<<dim3(Nb / 64, 512 / 64), 256>>>((const float*)px1, d1w, d1b,
                                                (float*)ph1, Nb, 512, 2048);
    k_gemm<1><<<dim3(Nb / 64, 512 / 64), 256>>>((const float*)ph1, d2w, d2b,
                                                (float*)ph2, Nb, 512, 512);

    k_heads<<<(Nb * 32 + 255) / 256, 256>>>((const float*)ph2, bboxes, cls,
                                            regw, regb, scw, scb, out, Nb);
}